// round 11
// baseline (speedup 1.0000x reference)
#include <cuda_runtime.h>

#define B_ 128
#define T_ 4096
#define I_ 64
#define H_ 128
#define G_ 384   /* 3*H */
#define C_ 2
#define ALPHA_ 0.3f
#define BETA_  0.5f

#define CH_   256   /* EMA chunk length  */
#define HALO_ 64    /* EMA warm-up halo: trunc err ~0.5^64 */

// Scratch (device globals: allocation-free per harness rules)
__device__ float g_x2[(long)B_ * T_ * I_];            // 134 MB
__device__ float g_xp[(long)B_ * T_ * G_ + 3 * G_];   // 805 MB (+3-row pad)
__device__ float g_st11[B_ * C_];
__device__ float g_st12[B_ * C_];

// ---------------- packed f32x2 helpers (sm_100+) ----------------
__device__ __forceinline__ unsigned long long pack2_(float lo, float hi) {
    unsigned long long r;
    asm("mov.b64 %0, {%1, %2};" : "=l"(r) : "f"(lo), "f"(hi));
    return r;
}
__device__ __forceinline__ float2 unpack2_(unsigned long long v) {
    float2 r;
    asm("mov.b64 {%0, %1}, %2;" : "=f"(r.x), "=f"(r.y) : "l"(v));
    return r;
}
__device__ __forceinline__ void fma2_(unsigned long long& d,
                                      unsigned long long a,
                                      unsigned long long b) {
    asm("fma.rn.f32x2 %0, %1, %2, %0;" : "+l"(d) : "l"(a), "l"(b));
}
__device__ __forceinline__ float tanh_hw_(float x) {
    float r;
    asm("tanh.approx.f32 %0, %1;" : "=f"(r) : "f"(x));
    return r;
}
__device__ __forceinline__ float sigm_hw_(float x) {
    return fmaf(tanh_hw_(0.5f * x), 0.5f, 0.5f);
}

// 2-way h swizzle: 16B chunk (2k+p) holds half-p chunk k  (k=0..15)
// h[j]: p=j>>6, k=(j>>2)&15, e=j&3 -> word 8k + 4p + e
__device__ __forceinline__ int hsw2_word_(int j) {
    int p = j >> 6, k = (j >> 2) & 15, e = j & 3;
    return 8 * k + 4 * p + e;
}

// ---------------------------------------------------------------------------
// Kernel 1: chained EMAs, chunked-parallel with decay halo.  (unchanged)
// ---------------------------------------------------------------------------
__global__ __launch_bounds__(64) void ema_kernel(const float* __restrict__ x) {
    int nchunk = T_ / CH_;
    int c = blockIdx.x % nchunk;
    int b = blockIdx.x / nchunk;
    int i = threadIdx.x;

    const float* xin = x + (long)b * T_ * I_ + i;
    float* o = g_x2 + (long)b * T_ * I_ + i;

    int t0 = c * CH_;
    int ts = (c == 0) ? 0 : (t0 - HALO_);

    float x1 = xin[(long)ts * I_];
    float x2 = x1;

#pragma unroll 4
    for (int t = ts + 1; t < t0; ++t) {
        float xt = xin[(long)t * I_];
        x1 = fmaf(ALPHA_, x1, (1.f - ALPHA_) * xt);
        x2 = fmaf(BETA_, x2, (1.f - BETA_) * x1);
    }

    if (c == 0) o[0] = x2;
    int tb = (c == 0) ? 1 : t0;
#pragma unroll 4
    for (int t = tb; t < t0 + CH_; ++t) {
        float xt = xin[(long)t * I_];
        x1 = fmaf(ALPHA_, x1, (1.f - ALPHA_) * xt);
        x2 = fmaf(BETA_, x2, (1.f - BETA_) * x1);
        o[(long)t * I_] = x2;
    }

    if (c == nchunk - 1 && (i == 1 || i == 2)) {
        g_st11[b * C_ + (i - 1)] = x1;
        g_st12[b * C_ + (i - 1)] = x2;
    }
}

// ---------------------------------------------------------------------------
// Kernel 2: xp = x2 @ W_ih^T + b_ih  (f32x2 packed; unchanged)
// ---------------------------------------------------------------------------
__global__ __launch_bounds__(384) void xp_gemm_kernel(
    const float* __restrict__ W_ih, const float* __restrict__ b_ih) {
    __shared__ __align__(16) float xs[64 * I_];  // 16 KB
    int m0 = blockIdx.x * 64;
    int g = threadIdx.x;

    {
        const float4* src = (const float4*)(g_x2 + (long)m0 * I_);
        float4* dst = (float4*)xs;
        for (int idx = g; idx < (64 * I_) / 4; idx += 384) dst[idx] = src[idx];
    }

    unsigned long long w2[I_ / 2];
    {
        const unsigned long long* wrow =
            (const unsigned long long*)(W_ih + g * I_);
#pragma unroll
        for (int k = 0; k < I_ / 2; ++k) w2[k] = wrow[k];
    }
    float bias = b_ih[g];
    __syncthreads();

    for (int r = 0; r < 64; ++r) {
        unsigned long long acc0 = pack2_(bias, 0.f);
        unsigned long long acc1 = pack2_(0.f, 0.f);
        const ulonglong2* row8 = (const ulonglong2*)(xs + r * I_);
#pragma unroll
        for (int k = 0; k < I_ / 4; ++k) {
            ulonglong2 v = row8[k];
            fma2_(acc0, w2[2 * k + 0], v.x);
            fma2_(acc1, w2[2 * k + 1], v.y);
        }
        float2 a0 = unpack2_(acc0);
        float2 a1 = unpack2_(acc1);
        g_xp[(long)(m0 + r) * G_ + g] = (a0.x + a1.x) + (a0.y + a1.y);
    }
}

// ---------------------------------------------------------------------------
// Kernel 3: GRU scan — TWO batches per CTA, DOUBLE-BUFFERED h (race-free
// single barrier). 64 CTAs, 256 threads. Thread (j = tid/2, p = tid&1):
// p-th 64-wide K-half of W_hh rows {j, 128+j, 256+j}, shared by batches.
// t-loop unrolled x2 so read/write buffers are compile-time.
// ---------------------------------------------------------------------------
__global__ __launch_bounds__(256, 1) void gru_kernel(
    const float* __restrict__ W_hh, const float* __restrict__ b_hh,
    const float* __restrict__ W_fc, const float* __restrict__ b_fc,
    float* __restrict__ out) {
    __shared__ __align__(16) float shwA0[H_], shwA1[H_];  // batch A ping/pong
    __shared__ __align__(16) float shwB0[H_], shwB1[H_];  // batch B ping/pong

    int tid = threadIdx.x;
    int j = tid >> 1;
    int p = tid & 1;
    int b0 = 2 * blockIdx.x;                  // batch A; batch B = b0+1

    // weight halves: rows j (r), 128+j (z), 256+j (n), cols [64p, 64p+64)
    unsigned long long wr[32], wz[32], wn[32];
    {
        const unsigned long long* rr =
            (const unsigned long long*)(W_hh + (j)*H_ + 64 * p);
        const unsigned long long* rz =
            (const unsigned long long*)(W_hh + (H_ + j) * H_ + 64 * p);
        const unsigned long long* rn =
            (const unsigned long long*)(W_hh + (2 * H_ + j) * H_ + 64 * p);
#pragma unroll
        for (int k = 0; k < 32; ++k) { wr[k] = rr[k]; wz[k] = rz[k]; wn[k] = rn[k]; }
    }

    float b_r = b_hh[j];            // folded on p0
    float b_z = b_hh[H_ + j];       // folded on p1
    float b_n = b_hh[2 * H_ + j];   // folded on p1

    // gi streams (prefetch depth 2), batch B via constant offset OB:
    //   gpA: p0 -> i_r (col j),    p1 -> i_z (col H+j)
    //   gpN: p0 -> i_n (col 2H+j), p1 -> dup i_z (unused)
    const long OB = (long)T_ * G_;
    const float* gpA = g_xp + (long)b0 * T_ * G_ + (p ? H_ + j : j);
    const float* gpN = gpA + (p ? 0 : 2 * H_);
    float a0A = gpA[0],  a1A = gpA[G_];
    float n0A = gpN[0],  n1A = gpN[G_];
    float a0B = gpA[OB], a1B = gpA[OB + G_];
    float n0B = gpN[OB], n1B = gpN[OB + G_];
    gpA += 2 * G_;
    gpN += 2 * G_;

    if (tid < H_) { shwA0[tid] = 0.f; shwA1[tid] = 0.f;
                    shwB0[tid] = 0.f; shwB1[tid] = 0.f; }
    float hprevA = 0.f, hprevB = 0.f;
    int hw = hsw2_word_(j);
    __syncthreads();

// One GRU step for both batches: read h from R-buffers, write to W-buffers.
// Race-free: stores never touch the buffer being read this step.
#define GRU_STEP(RA, WA, RB, WB)                                             \
    do {                                                                     \
        float a2A = gpA[0];  float a2B = gpA[OB];                            \
        float n2A = gpN[0];  float n2B = gpN[OB];                            \
        gpA += G_; gpN += G_;                                                \
        const ulonglong2* hswA = (const ulonglong2*)(RA);                    \
        const ulonglong2* hswB = (const ulonglong2*)(RB);                    \
        unsigned long long arA = pack2_(p ? 0.f : b_r + a0A, 0.f);           \
        unsigned long long azA = pack2_(p ? b_z + a0A : 0.f, 0.f);           \
        unsigned long long anA = pack2_(p ? b_n : 0.f, 0.f);                 \
        unsigned long long arB = pack2_(p ? 0.f : b_r + a0B, 0.f);           \
        unsigned long long azB = pack2_(p ? b_z + a0B : 0.f, 0.f);           \
        unsigned long long anB = pack2_(p ? b_n : 0.f, 0.f);                 \
        _Pragma("unroll")                                                    \
        for (int k = 0; k < 16; ++k) {                                       \
            ulonglong2 hvA = hswA[2 * k + p];                                \
            ulonglong2 hvB = hswB[2 * k + p];                                \
            fma2_(arA, wr[2 * k + 0], hvA.x);                                \
            fma2_(arA, wr[2 * k + 1], hvA.y);                                \
            fma2_(azA, wz[2 * k + 0], hvA.x);                                \
            fma2_(azA, wz[2 * k + 1], hvA.y);                                \
            fma2_(anA, wn[2 * k + 0], hvA.x);                                \
            fma2_(anA, wn[2 * k + 1], hvA.y);                                \
            fma2_(arB, wr[2 * k + 0], hvB.x);                                \
            fma2_(arB, wr[2 * k + 1], hvB.y);                                \
            fma2_(azB, wz[2 * k + 0], hvB.x);                                \
            fma2_(azB, wz[2 * k + 1], hvB.y);                                \
            fma2_(anB, wn[2 * k + 0], hvB.x);                                \
            fma2_(anB, wn[2 * k + 1], hvB.y);                                \
        }                                                                    \
        float2 f_;                                                           \
        f_ = unpack2_(arA); float ArA = f_.x + f_.y;                         \
        f_ = unpack2_(azA); float AzA = f_.x + f_.y;                         \
        f_ = unpack2_(anA); float GnA = f_.x + f_.y;                         \
        f_ = unpack2_(arB); float ArB = f_.x + f_.y;                         \
        f_ = unpack2_(azB); float AzB = f_.x + f_.y;                         \
        f_ = unpack2_(anB); float GnB = f_.x + f_.y;                         \
        ArA += __shfl_xor_sync(0xffffffffu, ArA, 1);                         \
        AzA += __shfl_xor_sync(0xffffffffu, AzA, 1);                         \
        GnA += __shfl_xor_sync(0xffffffffu, GnA, 1);                         \
        ArB += __shfl_xor_sync(0xffffffffu, ArB, 1);                         \
        AzB += __shfl_xor_sync(0xffffffffu, AzB, 1);                         \
        GnB += __shfl_xor_sync(0xffffffffu, GnB, 1);                         \
        if (p == 0) {                                                        \
            float rA = sigm_hw_(ArA);                                        \
            float zA = sigm_hw_(AzA);                                        \
            float nA = tanh_hw_(fmaf(rA, GnA, n0A));                         \
            hprevA = fmaf(zA, hprevA - nA, nA);                              \
            (WA)[hw] = hprevA;                                               \
            float rB = sigm_hw_(ArB);                                        \
            float zB = sigm_hw_(AzB);                                        \
            float nB = tanh_hw_(fmaf(rB, GnB, n0B));                         \
            hprevB = fmaf(zB, hprevB - nB, nB);                              \
            (WB)[hw] = hprevB;                                               \
        }                                                                    \
        __syncthreads();                                                     \
        a0A = a1A; a1A = a2A;  n0A = n1A; n1A = n2A;                         \
        a0B = a1B; a1B = a2B;  n0B = n1B; n1B = n2B;                         \
    } while (0)

    for (int t = 0; t < T_; t += 2) {
        GRU_STEP(shwA0, shwA1, shwB0, shwB1);  // even t: read 0, write 1
        GRU_STEP(shwA1, shwA0, shwB1, shwB0);  // odd  t: read 1, write 0
    }
#undef GRU_STEP
    // T_ even: final h lives in shwA0 / shwB0.

    if (tid < 2 * C_) {                       // FC head for both batches
        int bb = b0 + (tid >> 1);
        int c = tid & 1;
        const float* hh = (tid >> 1) ? shwB0 : shwA0;
        float o = b_fc[c];
        const float* wf = W_fc + c * H_;
#pragma unroll 8
        for (int jj = 0; jj < H_; ++jj)
            o = fmaf(hh[hsw2_word_(jj)], wf[jj], o);
        o = (o - BETA_ * g_st12[bb * C_ + c]) / (1.f - BETA_);
        o = (o - ALPHA_ * g_st11[bb * C_ + c]) / (1.f - ALPHA_);
        out[bb * C_ + c] = o;
    }
}

// ---------------------------------------------------------------------------
extern "C" void kernel_launch(void* const* d_in, const int* in_sizes, int n_in,
                              void* d_out, int out_size) {
    const float* x    = (const float*)d_in[0];
    const float* W_ih = (const float*)d_in[1];
    const float* W_hh = (const float*)d_in[2];
    const float* b_ih = (const float*)d_in[3];
    const float* b_hh = (const float*)d_in[4];
    const float* W_fc = (const float*)d_in[5];
    const float* b_fc = (const float*)d_in[6];
    float* out = (float*)d_out;

    ema_kernel<<<B_ * (T_ / CH_), 64>>>(x);
    xp_gemm_kernel<<<(B_ * T_) / 64, 384>>>(W_ih, b_ih);
    gru_kernel<<<B_ / 2, 256>>>(W_hh, b_hh, W_fc, b_fc, out);
}

// round 15
// speedup vs baseline: 1.8232x; 1.8232x over previous
#include <cuda_runtime.h>

#define B_ 128
#define T_ 4096
#define I_ 64
#define H_ 128
#define G_ 384   /* 3*H */
#define C_ 2
#define ALPHA_ 0.3f
#define BETA_  0.5f

#define CH_   256   /* EMA chunk length  */
#define HALO_ 64    /* EMA warm-up halo: trunc err ~0.5^64 */

// Scratch (device globals: allocation-free per harness rules)
__device__ float g_x2[(long)B_ * T_ * I_];            // 134 MB
__device__ float g_xp[(long)B_ * T_ * G_ + 3 * G_];   // 805 MB (+3-row pad)
__device__ float g_st11[B_ * C_];
__device__ float g_st12[B_ * C_];

// ---------------- packed f32x2 helpers (sm_100+) ----------------
__device__ __forceinline__ unsigned long long pack2_(float lo, float hi) {
    unsigned long long r;
    asm("mov.b64 %0, {%1, %2};" : "=l"(r) : "f"(lo), "f"(hi));
    return r;
}
__device__ __forceinline__ float2 unpack2_(unsigned long long v) {
    float2 r;
    asm("mov.b64 {%0, %1}, %2;" : "=f"(r.x), "=f"(r.y) : "l"(v));
    return r;
}
__device__ __forceinline__ void fma2_(unsigned long long& d,
                                      unsigned long long a,
                                      unsigned long long b) {
    asm("fma.rn.f32x2 %0, %1, %2, %0;" : "+l"(d) : "l"(a), "l"(b));
}
__device__ __forceinline__ float tanh_hw_(float x) {
    float r;
    asm("tanh.approx.f32 %0, %1;" : "=f"(r) : "f"(x));
    return r;
}
__device__ __forceinline__ float sigm_hw_(float x) {
    return fmaf(tanh_hw_(0.5f * x), 0.5f, 0.5f);
}
__device__ __forceinline__ unsigned int to_tf32_(float v) {
    unsigned int u;
    asm("cvt.rna.tf32.f32 %0, %1;" : "=r"(u) : "f"(v));
    return u;
}

// 2-way h swizzle: 16B chunk (2k+p) holds half-p chunk k  (k=0..15)
// h[j]: p=j>>6, k=(j>>2)&15, e=j&3 -> word 8k + 4p + e
__device__ __forceinline__ int hsw2_word_(int j) {
    int p = j >> 6, k = (j >> 2) & 15, e = j & 3;
    return 8 * k + 4 * p + e;
}

// ---------------------------------------------------------------------------
// Kernel 1: chained EMAs, chunked-parallel with decay halo.  (unchanged)
// ---------------------------------------------------------------------------
__global__ __launch_bounds__(64) void ema_kernel(const float* __restrict__ x) {
    int nchunk = T_ / CH_;
    int c = blockIdx.x % nchunk;
    int b = blockIdx.x / nchunk;
    int i = threadIdx.x;

    const float* xin = x + (long)b * T_ * I_ + i;
    float* o = g_x2 + (long)b * T_ * I_ + i;

    int t0 = c * CH_;
    int ts = (c == 0) ? 0 : (t0 - HALO_);

    float x1 = xin[(long)ts * I_];
    float x2 = x1;

#pragma unroll 4
    for (int t = ts + 1; t < t0; ++t) {
        float xt = xin[(long)t * I_];
        x1 = fmaf(ALPHA_, x1, (1.f - ALPHA_) * xt);
        x2 = fmaf(BETA_, x2, (1.f - BETA_) * x1);
    }

    if (c == 0) o[0] = x2;
    int tb = (c == 0) ? 1 : t0;
#pragma unroll 4
    for (int t = tb; t < t0 + CH_; ++t) {
        float xt = xin[(long)t * I_];
        x1 = fmaf(ALPHA_, x1, (1.f - ALPHA_) * xt);
        x2 = fmaf(BETA_, x2, (1.f - BETA_) * x1);
        o[(long)t * I_] = x2;
    }

    if (c == nchunk - 1 && (i == 1 || i == 2)) {
        g_st11[b * C_ + (i - 1)] = x1;
        g_st12[b * C_ + (i - 1)] = x2;
    }
}

// ---------------------------------------------------------------------------
// Kernel 2: xp = x2 @ W_ih^T + b_ih via tf32 mma.sync.m16n8k8.
// CTA: 384 threads (12 warps), M=64 rows, N=384, K=64.
// Warp w owns n-slice [32w, 32w+32) for ALL 64 rows:
//   B (weights) in REGISTERS: breg[kc][nt][2], 64 regs/thread, loaded once
//   from gmem (L2-resident W_ih). A tile in smem xs[64][68] (conflict-free).
//   Loop m-tiles 0..3; C-frags 16 regs per m-tile; bias folded into C init.
// ---------------------------------------------------------------------------
#define XS_STRIDE 68
__global__ __launch_bounds__(384) void xp_mma_kernel(
    const float* __restrict__ W_ih, const float* __restrict__ b_ih) {
    __shared__ unsigned int xs[64 * XS_STRIDE];   // 17408 B

    int tid = threadIdx.x;
    int m0 = blockIdx.x * 64;

    // fill A tile (coalesced gmem read, cvt to tf32)
    for (int idx = tid; idx < 64 * I_; idx += 384) {
        xs[(idx >> 6) * XS_STRIDE + (idx & 63)] = to_tf32_(g_x2[(long)m0 * I_ + idx]);
    }

    int w = tid >> 5;
    int lane = tid & 31;
    int lr = lane >> 2;           // 0..7
    int lc = lane & 3;            // 0..3
    int ng = 32 * w;              // warp's n-slice base

    // B fragments in registers: breg[kc][nt][r] = W_ih[(ng+8nt+lr)][8kc+lc+4r]
    unsigned int breg[8][4][2];
#pragma unroll
    for (int nt = 0; nt < 4; ++nt) {
        const float* wrow = W_ih + (ng + 8 * nt + lr) * I_ + lc;
#pragma unroll
        for (int kc = 0; kc < 8; ++kc) {
            breg[kc][nt][0] = to_tf32_(wrow[8 * kc]);
            breg[kc][nt][1] = to_tf32_(wrow[8 * kc + 4]);
        }
    }
    // bias per nt (cols ng + 8nt + 2lc, +1)
    float bl[4], bh[4];
#pragma unroll
    for (int nt = 0; nt < 4; ++nt) {
        bl[nt] = b_ih[ng + 8 * nt + 2 * lc];
        bh[nt] = b_ih[ng + 8 * nt + 2 * lc + 1];
    }
    __syncthreads();

#pragma unroll
    for (int mt = 0; mt < 4; ++mt) {
        int mb = 16 * mt;
        float c[4][4];
#pragma unroll
        for (int nt = 0; nt < 4; ++nt) {
            c[nt][0] = bl[nt]; c[nt][1] = bh[nt];   // row lr
            c[nt][2] = bl[nt]; c[nt][3] = bh[nt];   // row lr+8
        }
#pragma unroll
        for (int kc = 0; kc < 8; ++kc) {
            int k0 = 8 * kc;
            unsigned int a0 = xs[(mb + lr) * XS_STRIDE + k0 + lc];
            unsigned int a1 = xs[(mb + lr + 8) * XS_STRIDE + k0 + lc];
            unsigned int a2 = xs[(mb + lr) * XS_STRIDE + k0 + lc + 4];
            unsigned int a3 = xs[(mb + lr + 8) * XS_STRIDE + k0 + lc + 4];
#pragma unroll
            for (int nt = 0; nt < 4; ++nt) {
                asm volatile(
                    "mma.sync.aligned.m16n8k8.row.col.f32.tf32.tf32.f32 "
                    "{%0,%1,%2,%3}, {%4,%5,%6,%7}, {%8,%9}, {%0,%1,%2,%3};"
                    : "+f"(c[nt][0]), "+f"(c[nt][1]),
                      "+f"(c[nt][2]), "+f"(c[nt][3])
                    : "r"(a0), "r"(a1), "r"(a2), "r"(a3),
                      "r"(breg[kc][nt][0]), "r"(breg[kc][nt][1]));
            }
        }
        // store: rows m0+mb+lr (c0,c1), m0+mb+lr+8 (c2,c3); col ng+8nt+2lc
        long r0 = (long)(m0 + mb + lr) * G_;
        long r1 = r0 + 8 * G_;
#pragma unroll
        for (int nt = 0; nt < 4; ++nt) {
            int col = ng + 8 * nt + 2 * lc;
            *(float2*)(g_xp + r0 + col) = make_float2(c[nt][0], c[nt][1]);
            *(float2*)(g_xp + r1 + col) = make_float2(c[nt][2], c[nt][3]);
        }
    }
}

// ---------------------------------------------------------------------------
// Kernel 3: GRU scan — R9 shape (one batch/CTA, 256 threads, 2-way K-split)
// + DOUBLE-BUFFERED h => race-free with ONE barrier per step.
// Thread (j = tid/2, p = tid&1): p-th 64-wide K-half of W_hh rows
// {j, 128+j, 256+j} (96 f32x2 regs). t-loop unrolled x2 (static buffers).
// ---------------------------------------------------------------------------
__global__ __launch_bounds__(256, 1) void gru_kernel(
    const float* __restrict__ W_hh, const float* __restrict__ b_hh,
    const float* __restrict__ W_fc, const float* __restrict__ b_fc,
    float* __restrict__ out) {
    __shared__ __align__(16) float shw0[H_], shw1[H_];  // h ping/pong

    int tid = threadIdx.x;
    int j = tid >> 1;
    int p = tid & 1;
    int b = blockIdx.x;

    // weight halves: rows j (r), 128+j (z), 256+j (n), cols [64p, 64p+64)
    unsigned long long wr[32], wz[32], wn[32];
    {
        const unsigned long long* rr =
            (const unsigned long long*)(W_hh + (j)*H_ + 64 * p);
        const unsigned long long* rz =
            (const unsigned long long*)(W_hh + (H_ + j) * H_ + 64 * p);
        const unsigned long long* rn =
            (const unsigned long long*)(W_hh + (2 * H_ + j) * H_ + 64 * p);
#pragma unroll
        for (int k = 0; k < 32; ++k) { wr[k] = rr[k]; wz[k] = rz[k]; wn[k] = rn[k]; }
    }

    float b_r = b_hh[j];            // folded on p0
    float b_z = b_hh[H_ + j];       // folded on p1
    float b_n = b_hh[2 * H_ + j];   // folded on p1

    // gi streams (prefetch depth 2):
    //   gpA: p0 -> i_r (col j),    p1 -> i_z (col H+j)
    //   gpN: p0 -> i_n (col 2H+j), p1 -> dup i_z (unused)
    const float* gpA = g_xp + (long)b * T_ * G_ + (p ? H_ + j : j);
    const float* gpN = gpA + (p ? 0 : 2 * H_);
    float a0 = gpA[0], a1 = gpA[G_];
    float n0 = gpN[0], n1 = gpN[G_];
    gpA += 2 * G_;
    gpN += 2 * G_;

    if (tid < H_) { shw0[tid] = 0.f; shw1[tid] = 0.f; }
    float hprev = 0.f;
    int hw = hsw2_word_(j);
    __syncthreads();

// One GRU step: read h(t-1) from R buffer, write h(t) to W buffer.
// Race-free: stores never touch the buffer being read this step.
#define GRU_STEP(RBUF, WBUF)                                                 \
    do {                                                                     \
        float a2 = gpA[0]; float n2 = gpN[0];                                \
        gpA += G_; gpN += G_;                                                \
        const ulonglong2* hsw = (const ulonglong2*)(RBUF);                   \
        unsigned long long ar = pack2_(p ? 0.f : b_r + a0, 0.f);             \
        unsigned long long az = pack2_(p ? b_z + a0 : 0.f, 0.f);             \
        unsigned long long an = pack2_(p ? b_n : 0.f, 0.f);                  \
        _Pragma("unroll")                                                    \
        for (int k = 0; k < 16; ++k) {                                       \
            ulonglong2 hv = hsw[2 * k + p];                                  \
            fma2_(ar, wr[2 * k + 0], hv.x);                                  \
            fma2_(ar, wr[2 * k + 1], hv.y);                                  \
            fma2_(az, wz[2 * k + 0], hv.x);                                  \
            fma2_(az, wz[2 * k + 1], hv.y);                                  \
            fma2_(an, wn[2 * k + 0], hv.x);                                  \
            fma2_(an, wn[2 * k + 1], hv.y);                                  \
        }                                                                    \
        float2 f_;                                                           \
        f_ = unpack2_(ar); float Ar = f_.x + f_.y;                           \
        f_ = unpack2_(az); float Az = f_.x + f_.y;                           \
        f_ = unpack2_(an); float Gn = f_.x + f_.y;                           \
        Ar += __shfl_xor_sync(0xffffffffu, Ar, 1);                           \
        Az += __shfl_xor_sync(0xffffffffu, Az, 1);                           \
        Gn += __shfl_xor_sync(0xffffffffu, Gn, 1);                           \
        if (p == 0) {                                                        \
            float r = sigm_hw_(Ar);                                          \
            float z = sigm_hw_(Az);                                          \
            float n = tanh_hw_(fmaf(r, Gn, n0));                             \
            hprev = fmaf(z, hprev - n, n);                                   \
            (WBUF)[hw] = hprev;                                              \
        }                                                                    \
        __syncthreads();                                                     \
        a0 = a1; a1 = a2;  n0 = n1; n1 = n2;                                 \
    } while (0)

    for (int t = 0; t < T_; t += 2) {
        GRU_STEP(shw0, shw1);      // even t: read 0, write 1
        GRU_STEP(shw1, shw0);      // odd  t: read 1, write 0
    }
#undef GRU_STEP
    // T_ even: final h lives in shw0.

    if (tid < C_) {
        float o = b_fc[tid];
        const float* wf = W_fc + tid * H_;
#pragma unroll 8
        for (int jj = 0; jj < H_; ++jj)
            o = fmaf(shw0[hsw2_word_(jj)], wf[jj], o);
        o = (o - BETA_ * g_st12[b * C_ + tid]) / (1.f - BETA_);
        o = (o - ALPHA_ * g_st11[b * C_ + tid]) / (1.f - ALPHA_);
        out[b * C_ + tid] = o;
    }
}

// ---------------------------------------------------------------------------
extern "C" void kernel_launch(void* const* d_in, const int* in_sizes, int n_in,
                              void* d_out, int out_size) {
    const float* x    = (const float*)d_in[0];
    const float* W_ih = (const float*)d_in[1];
    const float* W_hh = (const float*)d_in[2];
    const float* b_ih = (const float*)d_in[3];
    const float* b_hh = (const float*)d_in[4];
    const float* W_fc = (const float*)d_in[5];
    const float* b_fc = (const float*)d_in[6];
    float* out = (float*)d_out;

    ema_kernel<<<B_ * (T_ / CH_), 64>>>(x);
    xp_mma_kernel<<<(B_ * T_) / 64, 384>>>(W_ih, b_ih);
    gru_kernel<<<B_, 256>>>(W_hh, b_hh, W_fc, b_fc, out);
}

// round 16
// speedup vs baseline: 1.8257x; 1.0013x over previous
#include <cuda_runtime.h>

#define B_ 128
#define T_ 4096
#define I_ 64
#define H_ 128
#define G_ 384   /* 3*H */
#define C_ 2
#define ALPHA_ 0.3f
#define BETA_  0.5f

#define CH_   256   /* EMA chunk length  */
#define HALO_ 64    /* EMA warm-up halo: trunc err ~0.5^64 */

// Scratch (device globals: allocation-free per harness rules)
__device__ float g_x2[(long)B_ * T_ * I_];            // 134 MB
__device__ float g_xp[(long)B_ * T_ * G_ + 3 * G_];   // 805 MB (+3-row pad)
__device__ float g_st11[B_ * C_];
__device__ float g_st12[B_ * C_];

// ---------------- packed f32x2 helpers (sm_100+) ----------------
__device__ __forceinline__ unsigned long long pack2_(float lo, float hi) {
    unsigned long long r;
    asm("mov.b64 %0, {%1, %2};" : "=l"(r) : "f"(lo), "f"(hi));
    return r;
}
__device__ __forceinline__ float2 unpack2_(unsigned long long v) {
    float2 r;
    asm("mov.b64 {%0, %1}, %2;" : "=f"(r.x), "=f"(r.y) : "l"(v));
    return r;
}
__device__ __forceinline__ void fma2_(unsigned long long& d,
                                      unsigned long long a,
                                      unsigned long long b) {
    asm("fma.rn.f32x2 %0, %1, %2, %0;" : "+l"(d) : "l"(a), "l"(b));
}
__device__ __forceinline__ float tanh_hw_(float x) {
    float r;
    asm("tanh.approx.f32 %0, %1;" : "=f"(r) : "f"(x));
    return r;
}
__device__ __forceinline__ float sigm_hw_(float x) {
    return fmaf(tanh_hw_(0.5f * x), 0.5f, 0.5f);
}
__device__ __forceinline__ unsigned int to_tf32_(float v) {
    unsigned int u;
    asm("cvt.rna.tf32.f32 %0, %1;" : "=r"(u) : "f"(v));
    return u;
}

// 2-way h swizzle: 16B chunk (2k+p) holds half-p chunk k  (k=0..15)
// h[j]: p=j>>6, k=(j>>2)&15, e=j&3 -> word 8k + 4p + e
__device__ __forceinline__ int hsw2_word_(int j) {
    int p = j >> 6, k = (j >> 2) & 15, e = j & 3;
    return 8 * k + 4 * p + e;
}

// ---------------------------------------------------------------------------
// Kernel 1: chained EMAs, chunked-parallel with decay halo.  (unchanged)
// ---------------------------------------------------------------------------
__global__ __launch_bounds__(64) void ema_kernel(const float* __restrict__ x) {
    int nchunk = T_ / CH_;
    int c = blockIdx.x % nchunk;
    int b = blockIdx.x / nchunk;
    int i = threadIdx.x;

    const float* xin = x + (long)b * T_ * I_ + i;
    float* o = g_x2 + (long)b * T_ * I_ + i;

    int t0 = c * CH_;
    int ts = (c == 0) ? 0 : (t0 - HALO_);

    float x1 = xin[(long)ts * I_];
    float x2 = x1;

#pragma unroll 4
    for (int t = ts + 1; t < t0; ++t) {
        float xt = xin[(long)t * I_];
        x1 = fmaf(ALPHA_, x1, (1.f - ALPHA_) * xt);
        x2 = fmaf(BETA_, x2, (1.f - BETA_) * x1);
    }

    if (c == 0) o[0] = x2;
    int tb = (c == 0) ? 1 : t0;
#pragma unroll 4
    for (int t = tb; t < t0 + CH_; ++t) {
        float xt = xin[(long)t * I_];
        x1 = fmaf(ALPHA_, x1, (1.f - ALPHA_) * xt);
        x2 = fmaf(BETA_, x2, (1.f - BETA_) * x1);
        o[(long)t * I_] = x2;
    }

    if (c == nchunk - 1 && (i == 1 || i == 2)) {
        g_st11[b * C_ + (i - 1)] = x1;
        g_st12[b * C_ + (i - 1)] = x2;
    }
}

// ---------------------------------------------------------------------------
// Kernel 2: xp = x2 @ W_ih^T + b_ih via tf32 mma.sync.m16n8k8.
// CTA: 384 threads (12 warps), M=64 rows, N=384, K=64.
// Warp w owns n-slice [32w, 32w+32) for ALL 64 rows:
//   B (weights) in REGISTERS: breg[kc][nt][2], 64 regs/thread, loaded once
//   from gmem (L2-resident W_ih). A tile in smem xs[64][68] (conflict-free).
//   Loop m-tiles 0..3; C-frags 16 regs per m-tile; bias folded into C init.
// ---------------------------------------------------------------------------
#define XS_STRIDE 68
__global__ __launch_bounds__(384) void xp_mma_kernel(
    const float* __restrict__ W_ih, const float* __restrict__ b_ih) {
    __shared__ unsigned int xs[64 * XS_STRIDE];   // 17408 B

    int tid = threadIdx.x;
    int m0 = blockIdx.x * 64;

    // fill A tile (coalesced gmem read, cvt to tf32)
    for (int idx = tid; idx < 64 * I_; idx += 384) {
        xs[(idx >> 6) * XS_STRIDE + (idx & 63)] = to_tf32_(g_x2[(long)m0 * I_ + idx]);
    }

    int w = tid >> 5;
    int lane = tid & 31;
    int lr = lane >> 2;           // 0..7
    int lc = lane & 3;            // 0..3
    int ng = 32 * w;              // warp's n-slice base

    // B fragments in registers: breg[kc][nt][r] = W_ih[(ng+8nt+lr)][8kc+lc+4r]
    unsigned int breg[8][4][2];
#pragma unroll
    for (int nt = 0; nt < 4; ++nt) {
        const float* wrow = W_ih + (ng + 8 * nt + lr) * I_ + lc;
#pragma unroll
        for (int kc = 0; kc < 8; ++kc) {
            breg[kc][nt][0] = to_tf32_(wrow[8 * kc]);
            breg[kc][nt][1] = to_tf32_(wrow[8 * kc + 4]);
        }
    }
    // bias per nt (cols ng + 8nt + 2lc, +1)
    float bl[4], bh[4];
#pragma unroll
    for (int nt = 0; nt < 4; ++nt) {
        bl[nt] = b_ih[ng + 8 * nt + 2 * lc];
        bh[nt] = b_ih[ng + 8 * nt + 2 * lc + 1];
    }
    __syncthreads();

#pragma unroll
    for (int mt = 0; mt < 4; ++mt) {
        int mb = 16 * mt;
        float c[4][4];
#pragma unroll
        for (int nt = 0; nt < 4; ++nt) {
            c[nt][0] = bl[nt]; c[nt][1] = bh[nt];   // row lr
            c[nt][2] = bl[nt]; c[nt][3] = bh[nt];   // row lr+8
        }
#pragma unroll
        for (int kc = 0; kc < 8; ++kc) {
            int k0 = 8 * kc;
            unsigned int a0 = xs[(mb + lr) * XS_STRIDE + k0 + lc];
            unsigned int a1 = xs[(mb + lr + 8) * XS_STRIDE + k0 + lc];
            unsigned int a2 = xs[(mb + lr) * XS_STRIDE + k0 + lc + 4];
            unsigned int a3 = xs[(mb + lr + 8) * XS_STRIDE + k0 + lc + 4];
#pragma unroll
            for (int nt = 0; nt < 4; ++nt) {
                asm volatile(
                    "mma.sync.aligned.m16n8k8.row.col.f32.tf32.tf32.f32 "
                    "{%0,%1,%2,%3}, {%4,%5,%6,%7}, {%8,%9}, {%0,%1,%2,%3};"
                    : "+f"(c[nt][0]), "+f"(c[nt][1]),
                      "+f"(c[nt][2]), "+f"(c[nt][3])
                    : "r"(a0), "r"(a1), "r"(a2), "r"(a3),
                      "r"(breg[kc][nt][0]), "r"(breg[kc][nt][1]));
            }
        }
        // store: rows m0+mb+lr (c0,c1), m0+mb+lr+8 (c2,c3); col ng+8nt+2lc
        long r0 = (long)(m0 + mb + lr) * G_;
        long r1 = r0 + 8 * G_;
#pragma unroll
        for (int nt = 0; nt < 4; ++nt) {
            int col = ng + 8 * nt + 2 * lc;
            *(float2*)(g_xp + r0 + col) = make_float2(c[nt][0], c[nt][1]);
            *(float2*)(g_xp + r1 + col) = make_float2(c[nt][2], c[nt][3]);
        }
    }
}

// ---------------------------------------------------------------------------
// Kernel 3: GRU scan — R9 shape (one batch/CTA, 256 threads, 2-way K-split)
// + DOUBLE-BUFFERED h => race-free with ONE barrier per step.
// Thread (j = tid/2, p = tid&1): p-th 64-wide K-half of W_hh rows
// {j, 128+j, 256+j} (96 f32x2 regs). t-loop unrolled x2 (static buffers).
// ---------------------------------------------------------------------------
__global__ __launch_bounds__(256, 1) void gru_kernel(
    const float* __restrict__ W_hh, const float* __restrict__ b_hh,
    const float* __restrict__ W_fc, const float* __restrict__ b_fc,
    float* __restrict__ out) {
    __shared__ __align__(16) float shw0[H_], shw1[H_];  // h ping/pong

    int tid = threadIdx.x;
    int j = tid >> 1;
    int p = tid & 1;
    int b = blockIdx.x;

    // weight halves: rows j (r), 128+j (z), 256+j (n), cols [64p, 64p+64)
    unsigned long long wr[32], wz[32], wn[32];
    {
        const unsigned long long* rr =
            (const unsigned long long*)(W_hh + (j)*H_ + 64 * p);
        const unsigned long long* rz =
            (const unsigned long long*)(W_hh + (H_ + j) * H_ + 64 * p);
        const unsigned long long* rn =
            (const unsigned long long*)(W_hh + (2 * H_ + j) * H_ + 64 * p);
#pragma unroll
        for (int k = 0; k < 32; ++k) { wr[k] = rr[k]; wz[k] = rz[k]; wn[k] = rn[k]; }
    }

    float b_r = b_hh[j];            // folded on p0
    float b_z = b_hh[H_ + j];       // folded on p1
    float b_n = b_hh[2 * H_ + j];   // folded on p1

    // gi streams (prefetch depth 2):
    //   gpA: p0 -> i_r (col j),    p1 -> i_z (col H+j)
    //   gpN: p0 -> i_n (col 2H+j), p1 -> dup i_z (unused)
    const float* gpA = g_xp + (long)b * T_ * G_ + (p ? H_ + j : j);
    const float* gpN = gpA + (p ? 0 : 2 * H_);
    float a0 = gpA[0], a1 = gpA[G_];
    float n0 = gpN[0], n1 = gpN[G_];
    gpA += 2 * G_;
    gpN += 2 * G_;

    if (tid < H_) { shw0[tid] = 0.f; shw1[tid] = 0.f; }
    float hprev = 0.f;
    int hw = hsw2_word_(j);
    __syncthreads();

// One GRU step: read h(t-1) from R buffer, write h(t) to W buffer.
// Race-free: stores never touch the buffer being read this step.
#define GRU_STEP(RBUF, WBUF)                                                 \
    do {                                                                     \
        float a2 = gpA[0]; float n2 = gpN[0];                                \
        gpA += G_; gpN += G_;                                                \
        const ulonglong2* hsw = (const ulonglong2*)(RBUF);                   \
        unsigned long long ar = pack2_(p ? 0.f : b_r + a0, 0.f);             \
        unsigned long long az = pack2_(p ? b_z + a0 : 0.f, 0.f);             \
        unsigned long long an = pack2_(p ? b_n : 0.f, 0.f);                  \
        _Pragma("unroll")                                                    \
        for (int k = 0; k < 16; ++k) {                                       \
            ulonglong2 hv = hsw[2 * k + p];                                  \
            fma2_(ar, wr[2 * k + 0], hv.x);                                  \
            fma2_(ar, wr[2 * k + 1], hv.y);                                  \
            fma2_(az, wz[2 * k + 0], hv.x);                                  \
            fma2_(az, wz[2 * k + 1], hv.y);                                  \
            fma2_(an, wn[2 * k + 0], hv.x);                                  \
            fma2_(an, wn[2 * k + 1], hv.y);                                  \
        }                                                                    \
        float2 f_;                                                           \
        f_ = unpack2_(ar); float Ar = f_.x + f_.y;                           \
        f_ = unpack2_(az); float Az = f_.x + f_.y;                           \
        f_ = unpack2_(an); float Gn = f_.x + f_.y;                           \
        Ar += __shfl_xor_sync(0xffffffffu, Ar, 1);                           \
        Az += __shfl_xor_sync(0xffffffffu, Az, 1);                           \
        Gn += __shfl_xor_sync(0xffffffffu, Gn, 1);                           \
        if (p == 0) {                                                        \
            float r = sigm_hw_(Ar);                                          \
            float z = sigm_hw_(Az);                                          \
            float n = tanh_hw_(fmaf(r, Gn, n0));                             \
            hprev = fmaf(z, hprev - n, n);                                   \
            (WBUF)[hw] = hprev;                                              \
        }                                                                    \
        __syncthreads();                                                     \
        a0 = a1; a1 = a2;  n0 = n1; n1 = n2;                                 \
    } while (0)

    for (int t = 0; t < T_; t += 2) {
        GRU_STEP(shw0, shw1);      // even t: read 0, write 1
        GRU_STEP(shw1, shw0);      // odd  t: read 1, write 0
    }
#undef GRU_STEP
    // T_ even: final h lives in shw0.

    if (tid < C_) {
        float o = b_fc[tid];
        const float* wf = W_fc + tid * H_;
#pragma unroll 8
        for (int jj = 0; jj < H_; ++jj)
            o = fmaf(shw0[hsw2_word_(jj)], wf[jj], o);
        o = (o - BETA_ * g_st12[b * C_ + tid]) / (1.f - BETA_);
        o = (o - ALPHA_ * g_st11[b * C_ + tid]) / (1.f - ALPHA_);
        out[b * C_ + tid] = o;
    }
}

// ---------------------------------------------------------------------------
extern "C" void kernel_launch(void* const* d_in, const int* in_sizes, int n_in,
                              void* d_out, int out_size) {
    const float* x    = (const float*)d_in[0];
    const float* W_ih = (const float*)d_in[1];
    const float* W_hh = (const float*)d_in[2];
    const float* b_ih = (const float*)d_in[3];
    const float* b_hh = (const float*)d_in[4];
    const float* W_fc = (const float*)d_in[5];
    const float* b_fc = (const float*)d_in[6];
    float* out = (float*)d_out;

    ema_kernel<<<B_ * (T_ / CH_), 64>>>(x);
    xp_mma_kernel<<<(B_ * T_) / 64, 384>>>(W_ih, b_ih);
    gru_kernel<<<B_, 256>>>(W_hh, b_hh, W_fc, b_fc, out);
}